// round 9
// baseline (speedup 1.0000x reference)
#include <cuda_runtime.h>
#include <cstddef>

#define BB 32
#define TT 2048
#define DD 512
#define HH 512
#define NCTA 128
#define JC 4
#define NTHR 512

// Scratch (device globals are the sanctioned allocation-free scratch)
__device__ float g_xT[(size_t)TT * DD * BB];    // x transposed: [t][d][b], 128 MB
__device__ float g_hbuf0[2][HH * BB];           // double-buffered h0, [j][b]
__device__ float g_hbuf1[2][HH * BB];           // double-buffered h1, [j][b]
__device__ unsigned g_flags[NCTA * 32];         // per-CTA arrival, own 128B line

__global__ void init_state_kernel() {
    int i = blockIdx.x * blockDim.x + threadIdx.x;
    if (i < HH * BB) { g_hbuf0[0][i] = 0.f; g_hbuf1[0][i] = 0.f; }
    if (i < NCTA * 32) g_flags[i] = 0u;
}

// x[b][t][d] -> xT[t][d][b]; one block per (t, 32-d tile), 32x33 smem tile.
__global__ __launch_bounds__(256) void transpose_kernel(const float* __restrict__ x) {
    __shared__ float tile[32][33];
    const int t  = blockIdx.x;
    const int d0 = blockIdx.y * 32;
    const int tx = threadIdx.x;        // 0..31
    const int ty = threadIdx.y;        // 0..7
    #pragma unroll
    for (int i = 0; i < 4; i++) {      // read: lane over d (coalesced)
        int b = ty + i * 8;
        tile[b][tx] = x[(size_t)b * TT * DD + (size_t)t * DD + d0 + tx];
    }
    __syncthreads();
    #pragma unroll
    for (int i = 0; i < 4; i++) {      // write: lane over b (coalesced)
        int r = ty + i * 8;            // local d
        g_xT[((size_t)t * DD + d0 + r) * BB + tx] = tile[tx][r];
    }
}

__device__ __forceinline__ float sigf(float x) { return 1.f / (1.f + __expf(-x)); }
__device__ __forceinline__ float tanhf_(float x) {
    x = fminf(15.f, fmaxf(-15.f, x));
    float e = __expf(2.f * x);
    return (e - 1.f) / (e + 1.f);
}

// Fully-fused 2-layer LSTM: persistent, 128 CTAs x 512 threads (16 warps).
// Wall step s: warps 0-7 compute L0 t=s (k over [x(s); h0(s-1)], K=1024),
// warps 8-15 compute L1 t=s-1 (k over [y0(s-1); h1(s-2)], K=1024).
// No standalone GEMM, no i2h scratch. One all-to-all flag barrier per step.
__global__ __launch_bounds__(NTHR, 1) void lstm_fused_kernel(
    const float* __restrict__ Wi0, const float* __restrict__ bi0,
    const float* __restrict__ Wh0, const float* __restrict__ bh0,
    const float* __restrict__ Wi1, const float* __restrict__ bi1,
    const float* __restrict__ Wh1, const float* __restrict__ bh1,
    float* __restrict__ yout, float* __restrict__ hc_out)
{
    extern __shared__ float sm[];
    float* ws0  = sm;                   // 1024*16  ([Wi0; Wh0] transposed)
    float* ws1  = ws0 + 1024 * 16;      // 1024*16  ([Wi1; Wh1] transposed)
    float* red0 = ws1 + 1024 * 16;      // 16*32*8
    float* red1 = red0 + 16 * 32 * 8;   // 16*32*8
    float* bs0  = red1 + 16 * 32 * 8;   // 16
    float* bs1  = bs0 + 16;             // 16
    float* cs0  = bs1 + 16;             // 128
    float* cs1  = cs0 + 128;            // 128

    const int tid = threadIdx.x;
    const int bid = blockIdx.x;
    const int j0 = bid * JC;

    // ---- stage weights transposed: ws[k*16 + rl], rl = g*4 + jj ----
    for (int idx = tid; idx < 1024 * 16; idx += NTHR) {
        int k = idx >> 4, rl = idx & 15;
        int g = rl >> 2, jj = rl & 3;
        ws0[idx] = (k < 512)
            ? Wi0[(size_t)(g * HH + j0 + jj) * DD + k]
            : Wh0[(size_t)(g * HH + j0 + jj) * HH + (k - 512)];
        ws1[idx] = (k < 512)
            ? Wi1[(size_t)(g * HH + j0 + jj) * HH + k]
            : Wh1[(size_t)(g * HH + j0 + jj) * HH + (k - 512)];
    }
    if (tid < 16) {
        int gg = tid >> 2, jx = tid & 3;
        bs0[tid] = bi0[gg * HH + j0 + jx] + bh0[gg * HH + j0 + jx];
        bs1[tid] = bi1[gg * HH + j0 + jx] + bh1[gg * HH + j0 + jx];
    }
    if (tid < 128) { cs0[tid] = 0.f; cs1[tid] = 0.f; }
    __syncthreads();

    const int w  = tid >> 5;           // warp 0..15
    const int rt = (tid >> 3) & 3;     // row quad
    const int bt = tid & 7;            // batch quad
    const float4* ws0_4 = reinterpret_cast<const float4*>(ws0);
    const float4* ws1_4 = reinterpret_cast<const float4*>(ws1);
    const float4* xT4   = reinterpret_cast<const float4*>(g_xT);

    for (int s = 0; s <= TT; s++) {
        // ---- FMA phase: one 128-k loop per warp ----
        {
            const float4* src4 = nullptr;
            const float4* wsrc4 = nullptr;
            int kb = 0, kw = 0;
            bool active = false;
            if (w < 8) {                 // L0, t = s
                if (s < TT) {
                    active = true;
                    wsrc4 = ws0_4;
                    kb = (w & 3) * 128;
                    if (w < 4) {         // x(s) part
                        src4 = xT4 + (size_t)s * (DD * BB / 4);
                        kw = kb;
                    } else {             // h0(s-1) part
                        src4 = reinterpret_cast<const float4*>(g_hbuf0[s & 1]);
                        kw = 512 + kb;
                    }
                }
            } else if (s >= 1) {         // L1, t = s-1
                active = true;
                wsrc4 = ws1_4;
                kb = ((w - 8) & 3) * 128;
                if (w < 12) {            // y0(s-1) part
                    src4 = reinterpret_cast<const float4*>(g_hbuf0[s & 1]);
                    kw = kb;
                } else {                 // h1(s-2) part
                    src4 = reinterpret_cast<const float4*>(g_hbuf1[(s - 1) & 1]);
                    kw = 512 + kb;
                }
            }
            if (active) {
                float acc[4][4];
                #pragma unroll
                for (int ri = 0; ri < 4; ri++)
                    #pragma unroll
                    for (int bi = 0; bi < 4; bi++) acc[ri][bi] = 0.f;
                #pragma unroll 4
                for (int c = 0; c < 16; c++) {        // 16 chunks x 8 k
                    float4 hp[8];
                    #pragma unroll
                    for (int i = 0; i < 8; i++)
                        hp[i] = __ldcg(&src4[(size_t)(kb + c * 8 + i) * 8 + bt]);
                    #pragma unroll
                    for (int i = 0; i < 8; i++) {
                        float4 wv = wsrc4[(kw + c * 8 + i) * 4 + rt];
                        acc[0][0] = fmaf(wv.x, hp[i].x, acc[0][0]);
                        acc[0][1] = fmaf(wv.x, hp[i].y, acc[0][1]);
                        acc[0][2] = fmaf(wv.x, hp[i].z, acc[0][2]);
                        acc[0][3] = fmaf(wv.x, hp[i].w, acc[0][3]);
                        acc[1][0] = fmaf(wv.y, hp[i].x, acc[1][0]);
                        acc[1][1] = fmaf(wv.y, hp[i].y, acc[1][1]);
                        acc[1][2] = fmaf(wv.y, hp[i].z, acc[1][2]);
                        acc[1][3] = fmaf(wv.y, hp[i].w, acc[1][3]);
                        acc[2][0] = fmaf(wv.z, hp[i].x, acc[2][0]);
                        acc[2][1] = fmaf(wv.z, hp[i].y, acc[2][1]);
                        acc[2][2] = fmaf(wv.z, hp[i].z, acc[2][2]);
                        acc[2][3] = fmaf(wv.z, hp[i].w, acc[2][3]);
                        acc[3][0] = fmaf(wv.w, hp[i].x, acc[3][0]);
                        acc[3][1] = fmaf(wv.w, hp[i].y, acc[3][1]);
                        acc[3][2] = fmaf(wv.w, hp[i].z, acc[3][2]);
                        acc[3][3] = fmaf(wv.w, hp[i].w, acc[3][3]);
                    }
                }
                float* red = (w < 8) ? red0 : red1;
                const int col = w & 7;
                #pragma unroll
                for (int ri = 0; ri < 4; ri++)
                    #pragma unroll
                    for (int bi = 0; bi < 4; bi++)
                        red[((rt * 4 + ri) * 32 + bt * 4 + bi) * 8 + col] = acc[ri][bi];
            }
        }
        __syncthreads();

        // ---- tails: tid<128 -> L0, tid in [128,256) -> L1 ----
        float   y_val = 0.f;           // deferred y1 store (L1 tail)
        size_t  y_idx = 0;
        bool    y_pend = false;

        if (tid < 128) {
            if (s < TT) {
                const int b = tid & 31, jj = tid >> 5;
                const int j = j0 + jj;
                float gate[4];
                #pragma unroll
                for (int g = 0; g < 4; g++) {
                    const int rr = g * 4 + jj;
                    const float4* rp = reinterpret_cast<const float4*>(&red0[(rr * 32 + b) * 8]);
                    float4 q0 = rp[0], q1 = rp[1];
                    gate[g] = ((q0.x + q0.y) + (q0.z + q0.w))
                            + ((q1.x + q1.y) + (q1.z + q1.w)) + bs0[rr];
                }
                float ig = sigf(gate[0]);
                float fg = sigf(gate[1]);
                float cg = tanhf_(gate[2]);
                float og = sigf(gate[3]);
                float c_new = fmaf(fg, cs0[tid], ig * cg);
                float h_new = og * tanhf_(c_new);
                cs0[tid] = c_new;
                g_hbuf0[(s + 1) & 1][j * BB + b] = h_new;
                if (s == TT - 1) {
                    hc_out[(size_t)0 * BB * HH + b * HH + j] = h_new;
                    hc_out[(size_t)2 * BB * HH + b * HH + j] = c_new;
                }
            }
        } else if (tid < 256) {
            if (s >= 1) {
                const int tt_ = tid - 128;
                const int b = tt_ & 31, jj = tt_ >> 5;
                const int j = j0 + jj;
                const int t = s - 1;
                float gate[4];
                #pragma unroll
                for (int g = 0; g < 4; g++) {
                    const int rr = g * 4 + jj;
                    const float4* rp = reinterpret_cast<const float4*>(&red1[(rr * 32 + b) * 8]);
                    float4 q0 = rp[0], q1 = rp[1];
                    gate[g] = ((q0.x + q0.y) + (q0.z + q0.w))
                            + ((q1.x + q1.y) + (q1.z + q1.w)) + bs1[rr];
                }
                float ig = sigf(gate[0]);
                float fg = sigf(gate[1]);
                float cg = tanhf_(gate[2]);
                float og = sigf(gate[3]);
                float c_new = fmaf(fg, cs1[tt_], ig * cg);
                float h_new = og * tanhf_(c_new);
                cs1[tt_] = c_new;
                g_hbuf1[s & 1][j * BB + b] = h_new;
                y_val = h_new;
                y_idx = ((size_t)b * TT + t) * HH + j;
                if (s < TT) {
                    y_pend = true;             // store after barrier announce
                } else {
                    yout[y_idx] = h_new;       // last step: no barrier follows
                }
                if (t == TT - 1) {
                    hc_out[(size_t)1 * BB * HH + b * HH + j] = h_new;
                    hc_out[(size_t)3 * BB * HH + b * HH + j] = c_new;
                }
            }
        }

        // ---- all-to-all flag barrier ----
        if (s < TT) {
            const unsigned e = (unsigned)(s + 1);
            __syncthreads();   // all h stores of this CTA done
            if (tid == 0)      // announce arrival on own 128B line
                asm volatile("st.release.gpu.u32 [%0], %1;"
                             :: "l"(&g_flags[bid * 32]), "r"(e) : "memory");
            if (y_pend) yout[y_idx] = y_val;   // overlap DRAM store w/ wait
            if (tid < NCTA) {  // every CTA polls every flag in parallel
                unsigned v;
                do {
                    asm volatile("ld.acquire.gpu.u32 %0, [%1];"
                                 : "=r"(v) : "l"(&g_flags[tid * 32]) : "memory");
                } while (v < e);
            }
            __syncthreads();
        }
    }
}

extern "C" void kernel_launch(void* const* d_in, const int* in_sizes, int n_in,
                              void* d_out, int out_size)
{
    (void)in_sizes; (void)n_in; (void)out_size;
    const float* x   = (const float*)d_in[0];
    const float* Wi0 = (const float*)d_in[1];
    const float* bi0 = (const float*)d_in[2];
    const float* Wh0 = (const float*)d_in[3];
    const float* bh0 = (const float*)d_in[4];
    const float* Wi1 = (const float*)d_in[5];
    const float* bi1 = (const float*)d_in[6];
    const float* Wh1 = (const float*)d_in[7];
    const float* bh1 = (const float*)d_in[8];
    float* out = (float*)d_out;

    const int SMEM = (1024*16 + 1024*16 + 16*32*8 + 16*32*8
                      + 16 + 16 + 128 + 128) * (int)sizeof(float);
    cudaFuncSetAttribute(lstm_fused_kernel,
                         cudaFuncAttributeMaxDynamicSharedMemorySize, SMEM);

    float* hc = out + (size_t)BB * TT * HH;

    dim3 tgrid(TT, DD / 32);
    transpose_kernel<<<tgrid, dim3(32, 8)>>>(x);
    init_state_kernel<<<64, 256>>>();
    lstm_fused_kernel<<<NCTA, NTHR, SMEM>>>(Wi0, bi0, Wh0, bh0,
                                            Wi1, bi1, Wh1, bh1, out, hc);
}

// round 10
// speedup vs baseline: 1.0101x; 1.0101x over previous
#include <cuda_runtime.h>
#include <cstddef>

#define BB 32
#define TT 2048
#define DD 512
#define HH 512
#define G4 2048
#define NCTA 128
#define JC 4
#define NTHR 384

// Scratch (device globals are the sanctioned allocation-free scratch)
__device__ float g_i2h[(size_t)BB * TT * G4];   // 512 MB, layer-0 i2h
__device__ float g_hbuf0[2][HH * BB];           // double-buffered h0, [j][b]
__device__ float g_hbuf1[2][HH * BB];           // double-buffered h1, [j][b]
__device__ unsigned g_flags[NCTA * 32];         // per-CTA arrival, own 128B line

__global__ void init_state_kernel() {
    int i = blockIdx.x * blockDim.x + threadIdx.x;
    if (i < HH * BB) { g_hbuf0[0][i] = 0.f; g_hbuf1[0][i] = 0.f; }
    if (i < NCTA * 32) g_flags[i] = 0u;
}

__device__ __forceinline__ float sigf(float x) { return 1.f / (1.f + __expf(-x)); }
__device__ __forceinline__ float tanhf_(float x) {
    x = fminf(15.f, fmaxf(-15.f, x));
    float e = __expf(2.f * x);
    return (e - 1.f) / (e + 1.f);
}

// Packed f32x2 FMA — Blackwell FFMA2, only reachable via PTX.
__device__ __forceinline__ unsigned long long fma2(
    unsigned long long a, unsigned long long b, unsigned long long c)
{
    unsigned long long d;
    asm("fma.rn.f32x2 %0, %1, %2, %3;" : "=l"(d) : "l"(a), "l"(b), "l"(c));
    return d;
}
union U2 { unsigned long long u; float2 f; };

// C[M,2048] = A[M,512] @ W[2048,512]^T + bias ; M = 65536, tiles 128x128x16.
__global__ __launch_bounds__(256, 2) void gemm_kernel(
    const float* __restrict__ A, const float* __restrict__ W,
    const float* __restrict__ bias, float* __restrict__ C)
{
    __shared__ float As[2][16][128];
    __shared__ float Ws[2][16][128];
    const int tid = threadIdx.x;
    const int tx = tid & 15, ty = tid >> 4;
    const int m0 = blockIdx.y * 128, n0 = blockIdx.x * 128;

    float acc[8][8];
    #pragma unroll
    for (int i = 0; i < 8; i++)
        #pragma unroll
        for (int j = 0; j < 8; j++) acc[i][j] = 0.f;

    const int lr = tid >> 1;
    const int lc = (tid & 1) * 2;
    const float* Arow = A + (size_t)(m0 + lr) * DD;
    const float* Wrow = W + (size_t)(n0 + lr) * DD;

    float4 ra0, ra1, rw0, rw1;
    ra0 = *reinterpret_cast<const float4*>(&Arow[lc * 4]);
    ra1 = *reinterpret_cast<const float4*>(&Arow[(lc + 1) * 4]);
    rw0 = *reinterpret_cast<const float4*>(&Wrow[lc * 4]);
    rw1 = *reinterpret_cast<const float4*>(&Wrow[(lc + 1) * 4]);
    {
        int c0 = lc, c1 = lc + 1;
        As[0][c0*4+0][lr] = ra0.x; As[0][c0*4+1][lr] = ra0.y;
        As[0][c0*4+2][lr] = ra0.z; As[0][c0*4+3][lr] = ra0.w;
        As[0][c1*4+0][lr] = ra1.x; As[0][c1*4+1][lr] = ra1.y;
        As[0][c1*4+2][lr] = ra1.z; As[0][c1*4+3][lr] = ra1.w;
        Ws[0][c0*4+0][lr] = rw0.x; Ws[0][c0*4+1][lr] = rw0.y;
        Ws[0][c0*4+2][lr] = rw0.z; Ws[0][c0*4+3][lr] = rw0.w;
        Ws[0][c1*4+0][lr] = rw1.x; Ws[0][c1*4+1][lr] = rw1.y;
        Ws[0][c1*4+2][lr] = rw1.z; Ws[0][c1*4+3][lr] = rw1.w;
    }
    __syncthreads();

    int p = 0;
    for (int k0 = 0; k0 < DD; k0 += 16) {
        const bool more = (k0 + 16 < DD);
        if (more) {
            ra0 = *reinterpret_cast<const float4*>(&Arow[k0 + 16 + lc * 4]);
            ra1 = *reinterpret_cast<const float4*>(&Arow[k0 + 16 + (lc + 1) * 4]);
            rw0 = *reinterpret_cast<const float4*>(&Wrow[k0 + 16 + lc * 4]);
            rw1 = *reinterpret_cast<const float4*>(&Wrow[k0 + 16 + (lc + 1) * 4]);
        }
        #pragma unroll
        for (int k = 0; k < 16; k++) {
            float4 a0 = *reinterpret_cast<const float4*>(&As[p][k][ty * 8]);
            float4 a1 = *reinterpret_cast<const float4*>(&As[p][k][ty * 8 + 4]);
            float4 b0 = *reinterpret_cast<const float4*>(&Ws[p][k][tx * 8]);
            float4 b1 = *reinterpret_cast<const float4*>(&Ws[p][k][tx * 8 + 4]);
            float av[8] = {a0.x,a0.y,a0.z,a0.w,a1.x,a1.y,a1.z,a1.w};
            float bv[8] = {b0.x,b0.y,b0.z,b0.w,b1.x,b1.y,b1.z,b1.w};
            #pragma unroll
            for (int i = 0; i < 8; i++)
                #pragma unroll
                for (int j = 0; j < 8; j++)
                    acc[i][j] = fmaf(av[i], bv[j], acc[i][j]);
        }
        if (more) {
            int q = 1 - p;
            int c0 = lc, c1 = lc + 1;
            As[q][c0*4+0][lr] = ra0.x; As[q][c0*4+1][lr] = ra0.y;
            As[q][c0*4+2][lr] = ra0.z; As[q][c0*4+3][lr] = ra0.w;
            As[q][c1*4+0][lr] = ra1.x; As[q][c1*4+1][lr] = ra1.y;
            As[q][c1*4+2][lr] = ra1.z; As[q][c1*4+3][lr] = ra1.w;
            Ws[q][c0*4+0][lr] = rw0.x; Ws[q][c0*4+1][lr] = rw0.y;
            Ws[q][c0*4+2][lr] = rw0.z; Ws[q][c0*4+3][lr] = rw0.w;
            Ws[q][c1*4+0][lr] = rw1.x; Ws[q][c1*4+1][lr] = rw1.y;
            Ws[q][c1*4+2][lr] = rw1.z; Ws[q][c1*4+3][lr] = rw1.w;
            __syncthreads();
            p = q;
        }
    }

    float4 bs0 = *reinterpret_cast<const float4*>(&bias[n0 + tx*8]);
    float4 bs1 = *reinterpret_cast<const float4*>(&bias[n0 + tx*8 + 4]);
    #pragma unroll
    for (int i = 0; i < 8; i++) {
        size_t row = (size_t)(m0 + ty*8 + i) * G4 + n0 + tx*8;
        float4 o0 = make_float4(acc[i][0]+bs0.x, acc[i][1]+bs0.y, acc[i][2]+bs0.z, acc[i][3]+bs0.w);
        float4 o1 = make_float4(acc[i][4]+bs1.x, acc[i][5]+bs1.y, acc[i][6]+bs1.z, acc[i][7]+bs1.w);
        *reinterpret_cast<float4*>(&C[row])     = o0;
        *reinterpret_cast<float4*>(&C[row + 4]) = o1;
    }
}

// Fused two-layer pipelined recurrence, spatial phase split, FFMA2 core.
// 384 threads / 12 warps: warps 0-3 -> L0 (t=s), warps 4-11 -> L1 (t=s-1).
// Weights stored DUPLICATED in smem ([k][2*rl]) so every fma.rn.f32x2
// multiplier is one aligned LDS.128 pair; h pairs come free from LDG.128.
__global__ __launch_bounds__(NTHR, 1) void lstm_fused_kernel(
    const float* __restrict__ Wh0, const float* __restrict__ bh0,
    const float* __restrict__ Wi1, const float* __restrict__ bi1,
    const float* __restrict__ Wh1, const float* __restrict__ bh1,
    const float* __restrict__ i2h, float* __restrict__ yout,
    float* __restrict__ hc_out)
{
    extern __shared__ float sm[];
    float* ws0  = sm;                   // 512*32  (dup)
    float* ws1  = ws0 + 512 * 32;       // 1024*32 (dup)
    float* red0 = ws1 + 1024 * 32;      // 16*32*4
    float* red1 = red0 + 16 * 32 * 4;   // 16*32*8
    float* pres = red1 + 16 * 32 * 8;   // 128 float4 = 512 floats
    float* bs0  = pres + 512;           // 16
    float* bs1  = bs0 + 16;             // 16
    float* cs0  = bs1 + 16;             // 128
    float* cs1  = cs0 + 128;            // 128

    const int tid = threadIdx.x;
    const int bid = blockIdx.x;
    const int j0 = bid * JC;

    // ---- stage weights transposed + duplicated: ws[k*32 + 2*rl{,+1}] ----
    for (int idx = tid; idx < 512 * 16; idx += NTHR) {
        int k = idx >> 4, rl = idx & 15;
        int g = rl >> 2, jj = rl & 3;
        float v = Wh0[(size_t)(g * HH + j0 + jj) * HH + k];
        ws0[k * 32 + 2 * rl] = v;  ws0[k * 32 + 2 * rl + 1] = v;
    }
    for (int idx = tid; idx < 1024 * 16; idx += NTHR) {
        int k = idx >> 4, rl = idx & 15;
        int g = rl >> 2, jj = rl & 3;
        float v = (k < 512)
            ? Wi1[(size_t)(g * HH + j0 + jj) * HH + k]
            : Wh1[(size_t)(g * HH + j0 + jj) * HH + (k - 512)];
        ws1[k * 32 + 2 * rl] = v;  ws1[k * 32 + 2 * rl + 1] = v;
    }
    if (tid < 16) {
        int gg = tid >> 2, jx = tid & 3;
        bs0[tid] = bh0[gg * HH + j0 + jx];
        bs1[tid] = bi1[gg * HH + j0 + jx] + bh1[gg * HH + j0 + jx];
    }
    if (tid < 128) { cs0[tid] = 0.f; cs1[tid] = 0.f; }
    __syncthreads();

    const int w  = tid >> 5;           // warp 0..11
    const int rt = (tid >> 3) & 3;     // row quad
    const int bt = tid & 7;            // batch quad
    const ulonglong2* ws0_2 = reinterpret_cast<const ulonglong2*>(ws0);
    const ulonglong2* ws1_2 = reinterpret_cast<const ulonglong2*>(ws1);
    float4* pres4 = reinterpret_cast<float4*>(pres);

    for (int s = 0; s <= TT; s++) {
        // coalesced i2h prefetch: thread (b,g) -> one float4 (4 consecutive j)
        float4 preq = make_float4(0.f, 0.f, 0.f, 0.f);
        if (tid < 128 && s < TT) {
            const int b_ = tid & 31, g_ = tid >> 5;
            preq = __ldcg(reinterpret_cast<const float4*>(
                i2h + ((size_t)b_ * TT + s) * G4 + (g_ << 9) + j0));
        }

        // ---- FMA phase: one 128-k FFMA2 loop per warp ----
        {
            const ulonglong2* src2 = nullptr;
            const ulonglong2* wsrc2 = nullptr;
            int kb = 0, kw = 0;
            bool active = false;
            if (w < 4) {                 // L0, t = s
                if (s < TT) {
                    active = true;
                    src2 = reinterpret_cast<const ulonglong2*>(g_hbuf0[s & 1]);
                    kb = w * 128;  kw = kb;  wsrc2 = ws0_2;
                }
            } else if (s >= 1) {         // L1, t = s-1
                active = true;
                wsrc2 = ws1_2;
                if (w < 8) {             // y0(t) part
                    src2 = reinterpret_cast<const ulonglong2*>(g_hbuf0[s & 1]);
                    kb = (w - 4) * 128;  kw = kb;
                } else {                 // h1(t-1) part
                    src2 = reinterpret_cast<const ulonglong2*>(g_hbuf1[(s - 1) & 1]);
                    kb = (w - 8) * 128;  kw = 512 + kb;
                }
            }
            if (active) {
                unsigned long long acc[4][2];
                #pragma unroll
                for (int ri = 0; ri < 4; ri++) { acc[ri][0] = 0ull; acc[ri][1] = 0ull; }
                #pragma unroll 4
                for (int c = 0; c < 16; c++) {        // 16 chunks x 8 k
                    ulonglong2 hp[8];
                    #pragma unroll
                    for (int i = 0; i < 8; i++)
                        hp[i] = __ldcg(&src2[(size_t)(kb + c * 8 + i) * 8 + bt]);
                    #pragma unroll
                    for (int i = 0; i < 8; i++) {
                        const int kk = kw + c * 8 + i;
                        ulonglong2 w01 = wsrc2[kk * 8 + rt * 2];      // rows 4rt,4rt+1 dup
                        ulonglong2 w23 = wsrc2[kk * 8 + rt * 2 + 1];  // rows 4rt+2,4rt+3 dup
                        acc[0][0] = fma2(w01.x, hp[i].x, acc[0][0]);
                        acc[0][1] = fma2(w01.x, hp[i].y, acc[0][1]);
                        acc[1][0] = fma2(w01.y, hp[i].x, acc[1][0]);
                        acc[1][1] = fma2(w01.y, hp[i].y, acc[1][1]);
                        acc[2][0] = fma2(w23.x, hp[i].x, acc[2][0]);
                        acc[2][1] = fma2(w23.x, hp[i].y, acc[2][1]);
                        acc[3][0] = fma2(w23.y, hp[i].x, acc[3][0]);
                        acc[3][1] = fma2(w23.y, hp[i].y, acc[3][1]);
                    }
                }
                if (w < 4) {
                    #pragma unroll
                    for (int ri = 0; ri < 4; ri++)
                        #pragma unroll
                        for (int p = 0; p < 2; p++) {
                            U2 v; v.u = acc[ri][p];
                            red0[((rt * 4 + ri) * 32 + bt * 4 + 2 * p) * 4 + w]     = v.f.x;
                            red0[((rt * 4 + ri) * 32 + bt * 4 + 2 * p + 1) * 4 + w] = v.f.y;
                        }
                } else {
                    #pragma unroll
                    for (int ri = 0; ri < 4; ri++)
                        #pragma unroll
                        for (int p = 0; p < 2; p++) {
                            U2 v; v.u = acc[ri][p];
                            red1[((rt * 4 + ri) * 32 + bt * 4 + 2 * p) * 8 + (w - 4)]     = v.f.x;
                            red1[((rt * 4 + ri) * 32 + bt * 4 + 2 * p + 1) * 8 + (w - 4)] = v.f.y;
                        }
                }
            }
        }
        // park prefetched i2h in smem (data long since arrived -> no stall)
        if (tid < 128 && s < TT) pres4[tid] = preq;
        __syncthreads();

        // ---- tails: tid<128 -> L0, tid in [128,256) -> L1 ----
        float   y_val = 0.f;           // deferred y1 store (L1 tail)
        size_t  y_idx = 0;
        bool    y_pend = false;

        if (tid < 128) {
            if (s < TT) {
                const int b = tid & 31, jj = tid >> 5;
                const int j = j0 + jj;
                float gate[4];
                #pragma unroll
                for (int g = 0; g < 4; g++) {
                    const int rr = g * 4 + jj;
                    float4 q0 = *reinterpret_cast<const float4*>(&red0[(rr * 32 + b) * 4]);
                    float pre = pres[(g * 32 + b) * 4 + jj];
                    gate[g] = ((q0.x + q0.y) + (q0.z + q0.w)) + pre + bs0[rr];
                }
                float ig = sigf(gate[0]);
                float fg = sigf(gate[1]);
                float cg = tanhf_(gate[2]);
                float og = sigf(gate[3]);
                float c_new = fmaf(fg, cs0[tid], ig * cg);
                float h_new = og * tanhf_(c_new);
                cs0[tid] = c_new;
                g_hbuf0[(s + 1) & 1][j * BB + b] = h_new;
                if (s == TT - 1) {
                    hc_out[(size_t)0 * BB * HH + b * HH + j] = h_new;
                    hc_out[(size_t)2 * BB * HH + b * HH + j] = c_new;
                }
            }
        } else if (tid < 256) {
            if (s >= 1) {
                const int tt_ = tid - 128;
                const int b = tt_ & 31, jj = tt_ >> 5;
                const int j = j0 + jj;
                const int t = s - 1;
                float gate[4];
                #pragma unroll
                for (int g = 0; g < 4; g++) {
                    const int rr = g * 4 + jj;
                    const float4* rp = reinterpret_cast<const float4*>(&red1[(rr * 32 + b) * 8]);
                    float4 q0 = rp[0], q1 = rp[1];
                    gate[g] = ((q0.x + q0.y) + (q0.z + q0.w))
                            + ((q1.x + q1.y) + (q1.z + q1.w)) + bs1[rr];
                }
                float ig = sigf(gate[0]);
                float fg = sigf(gate[1]);
                float cg = tanhf_(gate[2]);
                float og = sigf(gate[3]);
                float c_new = fmaf(fg, cs1[tt_], ig * cg);
                float h_new = og * tanhf_(c_new);
                cs1[tt_] = c_new;
                g_hbuf1[s & 1][j * BB + b] = h_new;
                y_val = h_new;
                y_idx = ((size_t)b * TT + t) * HH + j;
                if (s < TT) {
                    y_pend = true;             // store after barrier announce
                } else {
                    yout[y_idx] = h_new;       // last step: no barrier follows
                }
                if (t == TT - 1) {
                    hc_out[(size_t)1 * BB * HH + b * HH + j] = h_new;
                    hc_out[(size_t)3 * BB * HH + b * HH + j] = c_new;
                }
            }
        }

        // ---- all-to-all flag barrier ----
        if (s < TT) {
            const unsigned e = (unsigned)(s + 1);
            __syncthreads();   // all h stores of this CTA done
            if (tid == 0)      // announce arrival on own 128B line
                asm volatile("st.release.gpu.u32 [%0], %1;"
                             :: "l"(&g_flags[bid * 32]), "r"(e) : "memory");
            if (y_pend) yout[y_idx] = y_val;   // overlap DRAM store w/ wait
            if (tid < NCTA) {  // every CTA polls every flag in parallel
                unsigned v;
                do {
                    asm volatile("ld.acquire.gpu.u32 %0, [%1];"
                                 : "=r"(v) : "l"(&g_flags[tid * 32]) : "memory");
                } while (v < e);
            }
            __syncthreads();
        }
    }
}

extern "C" void kernel_launch(void* const* d_in, const int* in_sizes, int n_in,
                              void* d_out, int out_size)
{
    (void)in_sizes; (void)n_in; (void)out_size;
    const float* x   = (const float*)d_in[0];
    const float* Wi0 = (const float*)d_in[1];
    const float* bi0 = (const float*)d_in[2];
    const float* Wh0 = (const float*)d_in[3];
    const float* bh0 = (const float*)d_in[4];
    const float* Wi1 = (const float*)d_in[5];
    const float* bi1 = (const float*)d_in[6];
    const float* Wh1 = (const float*)d_in[7];
    const float* bh1 = (const float*)d_in[8];
    float* out = (float*)d_out;

    float* i2h_p;
    cudaGetSymbolAddress((void**)&i2h_p, g_i2h);

    const int SMEM = (512*32 + 1024*32 + 16*32*4 + 16*32*8 + 512
                      + 16 + 16 + 128 + 128) * (int)sizeof(float);
    cudaFuncSetAttribute(lstm_fused_kernel,
                         cudaFuncAttributeMaxDynamicSharedMemorySize, SMEM);

    dim3 ggrid(G4 / 128, (BB * TT) / 128);
    float* hc = out + (size_t)BB * TT * HH;

    gemm_kernel<<<ggrid, 256>>>(x, Wi0, bi0, i2h_p);          // L0 i2h only
    init_state_kernel<<<64, 256>>>();
    lstm_fused_kernel<<<NCTA, NTHR, SMEM>>>(Wh0, bh0, Wi1, bi1, Wh1, bh1,
                                            i2h_p, out, hc);
}

// round 11
// speedup vs baseline: 1.1741x; 1.1623x over previous
#include <cuda_runtime.h>
#include <cstddef>

#define BB 32
#define TT 2048
#define DD 512
#define HH 512
#define G4 2048
#define NCTA 128
#define JC 4
#define NTHR 384
#define GK 32
#define GSTRIDE 132

// Scratch (device globals are the sanctioned allocation-free scratch)
__device__ float g_i2h[(size_t)BB * TT * G4];   // 512 MB, layer-0 i2h
__device__ float g_hbuf0[2][HH * BB];           // double-buffered h0, [j][b]
__device__ float g_hbuf1[2][HH * BB];           // double-buffered h1, [j][b]
__device__ unsigned g_flags[NCTA * 32];         // per-CTA arrival, own 128B line

__global__ void init_state_kernel() {
    int i = blockIdx.x * blockDim.x + threadIdx.x;
    if (i < HH * BB) { g_hbuf0[0][i] = 0.f; g_hbuf1[0][i] = 0.f; }
    if (i < NCTA * 32) g_flags[i] = 0u;
}

__device__ __forceinline__ float sigf(float x) { return 1.f / (1.f + __expf(-x)); }
__device__ __forceinline__ float tanhf_(float x) {
    x = fminf(15.f, fmaxf(-15.f, x));
    float e = __expf(2.f * x);
    return (e - 1.f) / (e + 1.f);
}

__device__ __forceinline__ float tf32_hi(float x) {
    return __uint_as_float(__float_as_uint(x) & 0xFFFFE000u);
}

__device__ __forceinline__ void mma_tf32(float* d, const unsigned* a, const unsigned* b) {
    asm volatile(
        "mma.sync.aligned.m16n8k8.row.col.f32.tf32.tf32.f32 "
        "{%0,%1,%2,%3}, {%4,%5,%6,%7}, {%8,%9}, {%0,%1,%2,%3};"
        : "+f"(d[0]), "+f"(d[1]), "+f"(d[2]), "+f"(d[3])
        : "r"(a[0]), "r"(a[1]), "r"(a[2]), "r"(a[3]), "r"(b[0]), "r"(b[1]));
}

// C[M,2048] = A[M,512] @ W[2048,512]^T + bias via 3xTF32 tensor-core MMA.
// CTA tile 128x128, 8 warps x (64x32). Error ~2^-22 (fp32-equivalent).
__global__ __launch_bounds__(256) void gemm_tf32_kernel(
    const float* __restrict__ A, const float* __restrict__ W,
    const float* __restrict__ bias, float* __restrict__ C)
{
    extern __shared__ float gsm[];
    float* Ahs = gsm;                       // [GK][GSTRIDE]
    float* Als = Ahs + GK * GSTRIDE;
    float* Whs = Als + GK * GSTRIDE;
    float* Wls = Whs + GK * GSTRIDE;

    const int tid  = threadIdx.x;
    const int lane = tid & 31;
    const int w    = tid >> 5;              // warp 0..7
    const int wm   = w >> 2;                // 0..1 -> m offset wm*64
    const int wn   = w & 3;                 // 0..3 -> n offset wn*32
    const int lg   = lane >> 2;             // 0..7
    const int lt   = lane & 3;              // 0..3
    const int m0   = blockIdx.y * 128;
    const int n0   = blockIdx.x * 128;

    // staging coords: thread -> (row mr, k-quad kq)
    const int mr = tid >> 1;                // 0..127
    const int kq = (tid & 1) << 4;          // 0 | 16
    const float* Arow = A + (size_t)(m0 + mr) * DD;
    const float* Wrow = W + (size_t)(n0 + mr) * DD;

    float acc[4][4][4];
    #pragma unroll
    for (int mt = 0; mt < 4; mt++)
        #pragma unroll
        for (int nt = 0; nt < 4; nt++)
            #pragma unroll
            for (int i = 0; i < 4; i++) acc[mt][nt][i] = 0.f;

    for (int kc = 0; kc < DD; kc += GK) {
        __syncthreads();
        #pragma unroll
        for (int i = 0; i < 4; i++) {
            const int kk = kq + 4 * i;
            float4 va = *reinterpret_cast<const float4*>(Arow + kc + kk);
            float4 vw = *reinterpret_cast<const float4*>(Wrow + kc + kk);
            float h;
            h = tf32_hi(va.x); Ahs[(kk+0)*GSTRIDE + mr] = h; Als[(kk+0)*GSTRIDE + mr] = va.x - h;
            h = tf32_hi(va.y); Ahs[(kk+1)*GSTRIDE + mr] = h; Als[(kk+1)*GSTRIDE + mr] = va.y - h;
            h = tf32_hi(va.z); Ahs[(kk+2)*GSTRIDE + mr] = h; Als[(kk+2)*GSTRIDE + mr] = va.z - h;
            h = tf32_hi(va.w); Ahs[(kk+3)*GSTRIDE + mr] = h; Als[(kk+3)*GSTRIDE + mr] = va.w - h;
            h = tf32_hi(vw.x); Whs[(kk+0)*GSTRIDE + mr] = h; Wls[(kk+0)*GSTRIDE + mr] = vw.x - h;
            h = tf32_hi(vw.y); Whs[(kk+1)*GSTRIDE + mr] = h; Wls[(kk+1)*GSTRIDE + mr] = vw.y - h;
            h = tf32_hi(vw.z); Whs[(kk+2)*GSTRIDE + mr] = h; Wls[(kk+2)*GSTRIDE + mr] = vw.z - h;
            h = tf32_hi(vw.w); Whs[(kk+3)*GSTRIDE + mr] = h; Wls[(kk+3)*GSTRIDE + mr] = vw.w - h;
        }
        __syncthreads();

        #pragma unroll
        for (int k8 = 0; k8 < GK; k8 += 8) {
            unsigned ah[4][4], al[4][4], bh[4][2], bl[4][2];
            const int ka = (k8 + lt) * GSTRIDE;
            const int kb = (k8 + lt + 4) * GSTRIDE;
            #pragma unroll
            for (int mt = 0; mt < 4; mt++) {
                const int mb = wm * 64 + mt * 16 + lg;
                ah[mt][0] = __float_as_uint(Ahs[ka + mb]);
                ah[mt][1] = __float_as_uint(Ahs[ka + mb + 8]);
                ah[mt][2] = __float_as_uint(Ahs[kb + mb]);
                ah[mt][3] = __float_as_uint(Ahs[kb + mb + 8]);
                al[mt][0] = __float_as_uint(Als[ka + mb]);
                al[mt][1] = __float_as_uint(Als[ka + mb + 8]);
                al[mt][2] = __float_as_uint(Als[kb + mb]);
                al[mt][3] = __float_as_uint(Als[kb + mb + 8]);
            }
            #pragma unroll
            for (int nt = 0; nt < 4; nt++) {
                const int nb = wn * 32 + nt * 8 + lg;
                bh[nt][0] = __float_as_uint(Whs[ka + nb]);
                bh[nt][1] = __float_as_uint(Whs[kb + nb]);
                bl[nt][0] = __float_as_uint(Wls[ka + nb]);
                bl[nt][1] = __float_as_uint(Wls[kb + nb]);
            }
            #pragma unroll
            for (int mt = 0; mt < 4; mt++)
                #pragma unroll
                for (int nt = 0; nt < 4; nt++)
                    mma_tf32(acc[mt][nt], ah[mt], bh[nt]);
            #pragma unroll
            for (int mt = 0; mt < 4; mt++)
                #pragma unroll
                for (int nt = 0; nt < 4; nt++)
                    mma_tf32(acc[mt][nt], al[mt], bh[nt]);
            #pragma unroll
            for (int mt = 0; mt < 4; mt++)
                #pragma unroll
                for (int nt = 0; nt < 4; nt++)
                    mma_tf32(acc[mt][nt], ah[mt], bl[nt]);
        }
    }

    // epilogue: c0,c1 -> (row, col..col+1); c2,c3 -> (row+8, ...)
    #pragma unroll
    for (int mt = 0; mt < 4; mt++) {
        const int row = m0 + wm * 64 + mt * 16 + lg;
        #pragma unroll
        for (int nt = 0; nt < 4; nt++) {
            const int col = n0 + wn * 32 + nt * 8 + lt * 2;
            float2 bs = *reinterpret_cast<const float2*>(bias + col);
            float2 o0 = make_float2(acc[mt][nt][0] + bs.x, acc[mt][nt][1] + bs.y);
            float2 o1 = make_float2(acc[mt][nt][2] + bs.x, acc[mt][nt][3] + bs.y);
            *reinterpret_cast<float2*>(C + (size_t)row * G4 + col)       = o0;
            *reinterpret_cast<float2*>(C + (size_t)(row + 8) * G4 + col) = o1;
        }
    }
}

// Fused two-layer pipelined recurrence, spatial phase split (R8-proven form).
// 384 threads / 12 warps: warps 0-3 -> L0 (t=s), warps 4-11 -> L1 (t=s-1).
// 2049 wall steps; ONE all-to-all flag barrier each.
__global__ __launch_bounds__(NTHR, 1) void lstm_fused_kernel(
    const float* __restrict__ Wh0, const float* __restrict__ bh0,
    const float* __restrict__ Wi1, const float* __restrict__ bi1,
    const float* __restrict__ Wh1, const float* __restrict__ bh1,
    const float* __restrict__ i2h, float* __restrict__ yout,
    float* __restrict__ hc_out)
{
    extern __shared__ float sm[];
    float* ws0  = sm;                   // 512*16
    float* ws1  = ws0 + 512 * 16;       // 1024*16
    float* red0 = ws1 + 1024 * 16;      // 16*32*4
    float* red1 = red0 + 16 * 32 * 4;   // 16*32*8
    float* pres = red1 + 16 * 32 * 8;   // 128 float4 = 512 floats
    float* bs0  = pres + 512;           // 16
    float* bs1  = bs0 + 16;             // 16
    float* cs0  = bs1 + 16;             // 128
    float* cs1  = cs0 + 128;            // 128

    const int tid = threadIdx.x;
    const int bid = blockIdx.x;
    const int j0 = bid * JC;

    // ---- stage weights transposed: ws[k*16 + rl], rl = g*4 + jj ----
    for (int idx = tid; idx < 512 * 16; idx += NTHR) {
        int k = idx >> 4, rl = idx & 15;
        int g = rl >> 2, jj = rl & 3;
        ws0[idx] = Wh0[(size_t)(g * HH + j0 + jj) * HH + k];
    }
    for (int idx = tid; idx < 1024 * 16; idx += NTHR) {
        int k = idx >> 4, rl = idx & 15;
        int g = rl >> 2, jj = rl & 3;
        ws1[idx] = (k < 512)
            ? Wi1[(size_t)(g * HH + j0 + jj) * HH + k]
            : Wh1[(size_t)(g * HH + j0 + jj) * HH + (k - 512)];
    }
    if (tid < 16) {
        int gg = tid >> 2, jx = tid & 3;
        bs0[tid] = bh0[gg * HH + j0 + jx];
        bs1[tid] = bi1[gg * HH + j0 + jx] + bh1[gg * HH + j0 + jx];
    }
    if (tid < 128) { cs0[tid] = 0.f; cs1[tid] = 0.f; }
    __syncthreads();

    const int w  = tid >> 5;           // warp 0..11
    const int rt = (tid >> 3) & 3;     // row quad
    const int bt = tid & 7;            // batch quad
    const float4* ws0_4 = reinterpret_cast<const float4*>(ws0);
    const float4* ws1_4 = reinterpret_cast<const float4*>(ws1);
    float4* pres4 = reinterpret_cast<float4*>(pres);

    for (int s = 0; s <= TT; s++) {
        // coalesced i2h prefetch: thread (b,g) -> one float4 (4 consecutive j)
        float4 preq = make_float4(0.f, 0.f, 0.f, 0.f);
        if (tid < 128 && s < TT) {
            const int b_ = tid & 31, g_ = tid >> 5;
            preq = __ldcg(reinterpret_cast<const float4*>(
                i2h + ((size_t)b_ * TT + s) * G4 + (g_ << 9) + j0));
        }

        // ---- FMA phase: one 128-k loop per warp ----
        {
            const float4* src4 = nullptr;
            const float4* wsrc4 = nullptr;
            int kb = 0, kw = 0;
            bool active = false;
            if (w < 4) {                 // L0, t = s
                if (s < TT) {
                    active = true;
                    src4 = reinterpret_cast<const float4*>(g_hbuf0[s & 1]);
                    kb = w * 128;  kw = kb;  wsrc4 = ws0_4;
                }
            } else if (s >= 1) {         // L1, t = s-1
                active = true;
                wsrc4 = ws1_4;
                if (w < 8) {             // y0(t) part
                    src4 = reinterpret_cast<const float4*>(g_hbuf0[s & 1]);
                    kb = (w - 4) * 128;  kw = kb;
                } else {                 // h1(t-1) part
                    src4 = reinterpret_cast<const float4*>(g_hbuf1[(s - 1) & 1]);
                    kb = (w - 8) * 128;  kw = 512 + kb;
                }
            }
            if (active) {
                float acc[4][4];
                #pragma unroll
                for (int ri = 0; ri < 4; ri++)
                    #pragma unroll
                    for (int bi = 0; bi < 4; bi++) acc[ri][bi] = 0.f;
                #pragma unroll 4
                for (int c = 0; c < 16; c++) {        // 16 chunks x 8 k
                    float4 hp[8];
                    #pragma unroll
                    for (int i = 0; i < 8; i++)
                        hp[i] = __ldcg(&src4[(size_t)(kb + c * 8 + i) * 8 + bt]);
                    #pragma unroll
                    for (int i = 0; i < 8; i++) {
                        float4 wv = wsrc4[(kw + c * 8 + i) * 4 + rt];
                        acc[0][0] = fmaf(wv.x, hp[i].x, acc[0][0]);
                        acc[0][1] = fmaf(wv.x, hp[i].y, acc[0][1]);
                        acc[0][2] = fmaf(wv.x, hp[i].z, acc[0][2]);
                        acc[0][3] = fmaf(wv.x, hp[i].w, acc[0][3]);
                        acc[1][0] = fmaf(wv.y, hp[i].x, acc[1][0]);
                        acc[1][1] = fmaf(wv.y, hp[i].y, acc[1][1]);
                        acc[1][2] = fmaf(wv.y, hp[i].z, acc[1][2]);
                        acc[1][3] = fmaf(wv.y, hp[i].w, acc[1][3]);
                        acc[2][0] = fmaf(wv.z, hp[i].x, acc[2][0]);
                        acc[2][1] = fmaf(wv.z, hp[i].y, acc[2][1]);
                        acc[2][2] = fmaf(wv.z, hp[i].z, acc[2][2]);
                        acc[2][3] = fmaf(wv.z, hp[i].w, acc[2][3]);
                        acc[3][0] = fmaf(wv.w, hp[i].x, acc[3][0]);
                        acc[3][1] = fmaf(wv.w, hp[i].y, acc[3][1]);
                        acc[3][2] = fmaf(wv.w, hp[i].z, acc[3][2]);
                        acc[3][3] = fmaf(wv.w, hp[i].w, acc[3][3]);
                    }
                }
                if (w < 4) {
                    #pragma unroll
                    for (int ri = 0; ri < 4; ri++)
                        #pragma unroll
                        for (int bi = 0; bi < 4; bi++)
                            red0[((rt * 4 + ri) * 32 + bt * 4 + bi) * 4 + w] = acc[ri][bi];
                } else {
                    #pragma unroll
                    for (int ri = 0; ri < 4; ri++)
                        #pragma unroll
                        for (int bi = 0; bi < 4; bi++)
                            red1[((rt * 4 + ri) * 32 + bt * 4 + bi) * 8 + (w - 4)] = acc[ri][bi];
                }
            }
        }
        // park prefetched i2h in smem (data long since arrived -> no stall)
        if (tid < 128 && s < TT) pres4[tid] = preq;
        __syncthreads();

        // ---- tails: tid<128 -> L0, tid in [128,256) -> L1 ----
        float   y_val = 0.f;           // deferred y1 store (L1 tail)
        size_t  y_idx = 0;
        bool    y_pend = false;

        if (tid < 128) {
            if (s < TT) {
                const int b = tid & 31, jj = tid >> 5;
                const int j = j0 + jj;
                float gate[4];
                #pragma unroll
                for (int g = 0; g < 4; g++) {
                    const int rr = g * 4 + jj;
                    float4 q0 = *reinterpret_cast<const float4*>(&red0[(rr * 32 + b) * 4]);
                    float pre = pres[(g * 32 + b) * 4 + jj];
                    gate[g] = ((q0.x + q0.y) + (q0.z + q0.w)) + pre + bs0[rr];
                }
                float ig = sigf(gate[0]);
                float fg = sigf(gate[1]);
                float cg = tanhf_(gate[2]);
                float og = sigf(gate[3]);
                float c_new = fmaf(fg, cs0[tid], ig * cg);
                float h_new = og * tanhf_(c_new);
                cs0[tid] = c_new;
                g_hbuf0[(s + 1) & 1][j * BB + b] = h_new;
                if (s == TT - 1) {
                    hc_out[(size_t)0 * BB * HH + b * HH + j] = h_new;
                    hc_out[(size_t)2 * BB * HH + b * HH + j] = c_new;
                }
            }
        } else if (tid < 256) {
            if (s >= 1) {
                const int tt_ = tid - 128;
                const int b = tt_ & 31, jj = tt_ >> 5;
                const int j = j0 + jj;
                const int t = s - 1;
                float gate[4];
                #pragma unroll
                for (int g = 0; g < 4; g++) {
                    const int rr = g * 4 + jj;
                    const float4* rp = reinterpret_cast<const float4*>(&red1[(rr * 32 + b) * 8]);
                    float4 q0 = rp[0], q1 = rp[1];
                    gate[g] = ((q0.x + q0.y) + (q0.z + q0.w))
                            + ((q1.x + q1.y) + (q1.z + q1.w)) + bs1[rr];
                }
                float ig = sigf(gate[0]);
                float fg = sigf(gate[1]);
                float cg = tanhf_(gate[2]);
                float og = sigf(gate[3]);
                float c_new = fmaf(fg, cs1[tt_], ig * cg);
                float h_new = og * tanhf_(c_new);
                cs1[tt_] = c_new;
                g_hbuf1[s & 1][j * BB + b] = h_new;
                y_val = h_new;
                y_idx = ((size_t)b * TT + t) * HH + j;
                if (s < TT) {
                    y_pend = true;             // store after barrier announce
                } else {
                    yout[y_idx] = h_new;       // last step: no barrier follows
                }
                if (t == TT - 1) {
                    hc_out[(size_t)1 * BB * HH + b * HH + j] = h_new;
                    hc_out[(size_t)3 * BB * HH + b * HH + j] = c_new;
                }
            }
        }

        // ---- all-to-all flag barrier ----
        if (s < TT) {
            const unsigned e = (unsigned)(s + 1);
            __syncthreads();   // all h stores of this CTA done
            if (tid == 0)      // announce arrival on own 128B line
                asm volatile("st.release.gpu.u32 [%0], %1;"
                             :: "l"(&g_flags[bid * 32]), "r"(e) : "memory");
            if (y_pend) yout[y_idx] = y_val;   // overlap DRAM store w/ wait
            if (tid < NCTA) {  // every CTA polls every flag in parallel
                unsigned v;
                do {
                    asm volatile("ld.acquire.gpu.u32 %0, [%1];"
                                 : "=r"(v) : "l"(&g_flags[tid * 32]) : "memory");
                } while (v < e);
            }
            __syncthreads();
        }
    }
}

extern "C" void kernel_launch(void* const* d_in, const int* in_sizes, int n_in,
                              void* d_out, int out_size)
{
    (void)in_sizes; (void)n_in; (void)out_size;
    const float* x   = (const float*)d_in[0];
    const float* Wi0 = (const float*)d_in[1];
    const float* bi0 = (const float*)d_in[2];
    const float* Wh0 = (const float*)d_in[3];
    const float* bh0 = (const float*)d_in[4];
    const float* Wi1 = (const float*)d_in[5];
    const float* bi1 = (const float*)d_in[6];
    const float* Wh1 = (const float*)d_in[7];
    const float* bh1 = (const float*)d_in[8];
    float* out = (float*)d_out;

    float* i2h_p;
    cudaGetSymbolAddress((void**)&i2h_p, g_i2h);

    const int SMEM_G = 4 * GK * GSTRIDE * (int)sizeof(float);
    cudaFuncSetAttribute(gemm_tf32_kernel,
                         cudaFuncAttributeMaxDynamicSharedMemorySize, SMEM_G);

    const int SMEM = (512*16 + 1024*16 + 16*32*4 + 16*32*8 + 512
                      + 16 + 16 + 128 + 128) * (int)sizeof(float);
    cudaFuncSetAttribute(lstm_fused_kernel,
                         cudaFuncAttributeMaxDynamicSharedMemorySize, SMEM);

    dim3 ggrid(G4 / 128, (BB * TT) / 128);
    float* hc = out + (size_t)BB * TT * HH;

    gemm_tf32_kernel<<<ggrid, 256, SMEM_G>>>(x, Wi0, bi0, i2h_p);  // L0 i2h
    init_state_kernel<<<64, 256>>>();
    lstm_fused_kernel<<<NCTA, NTHR, SMEM>>>(Wh0, bh0, Wi1, bi1, Wh1, bh1,
                                            i2h_p, out, hc);
}

// round 15
// speedup vs baseline: 1.1774x; 1.0028x over previous
#include <cuda_runtime.h>
#include <cuda_bf16.h>
#include <cstddef>

#define BB 32
#define TT 2048
#define DD 512
#define HH 512
#define G4 2048
#define NCTA 128
#define JC 4
#define NTHR 384
#define GK 32
#define GSTRIDE 132

// Scratch (device globals are the sanctioned allocation-free scratch)
__device__ float g_i2h[(size_t)BB * TT * G4];        // 512 MB, layer-0 i2h
__device__ unsigned short g_h0h[2][BB * HH];         // h0 bf16 hi, [b][k]
__device__ unsigned short g_h0l[2][BB * HH];         // h0 bf16 lo
__device__ unsigned short g_h1h[2][BB * HH];         // h1 bf16 hi
__device__ unsigned short g_h1l[2][BB * HH];         // h1 bf16 lo
__device__ unsigned g_flags[NCTA * 32];              // per-CTA arrival flags

__global__ void init_state_kernel() {
    int i = blockIdx.x * blockDim.x + threadIdx.x;
    if (i < BB * HH) {
        g_h0h[0][i] = 0; g_h0l[0][i] = 0;
        g_h1h[0][i] = 0; g_h1l[0][i] = 0;
    }
    if (i < NCTA * 32) g_flags[i] = 0u;
}

__device__ __forceinline__ float sigf(float x) { return 1.f / (1.f + __expf(-x)); }
__device__ __forceinline__ float tanhf_(float x) {
    x = fminf(15.f, fmaxf(-15.f, x));
    float e = __expf(2.f * x);
    return (e - 1.f) / (e + 1.f);
}

union BFU { __nv_bfloat16 b; unsigned short u; };
__device__ __forceinline__ void bf_split(float v, unsigned short& hi, unsigned short& lo) {
    BFU h; h.b = __float2bfloat16_rn(v);
    BFU l; l.b = __float2bfloat16_rn(v - __bfloat162float(h.b));
    hi = h.u; lo = l.u;
}
__device__ __forceinline__ unsigned bf_pack(unsigned short lo16, unsigned short hi16) {
    return (unsigned)lo16 | ((unsigned)hi16 << 16);
}

__device__ __forceinline__ float tf32_hi(float x) {
    return __uint_as_float(__float_as_uint(x) & 0xFFFFE000u);
}

__device__ __forceinline__ void mma_tf32(float* d, const unsigned* a, const unsigned* b) {
    asm volatile(
        "mma.sync.aligned.m16n8k8.row.col.f32.tf32.tf32.f32 "
        "{%0,%1,%2,%3}, {%4,%5,%6,%7}, {%8,%9}, {%0,%1,%2,%3};"
        : "+f"(d[0]), "+f"(d[1]), "+f"(d[2]), "+f"(d[3])
        : "r"(a[0]), "r"(a[1]), "r"(a[2]), "r"(a[3]), "r"(b[0]), "r"(b[1]));
}

__device__ __forceinline__ void mma_bf16(float* d, const unsigned* a, const unsigned* b) {
    asm volatile(
        "mma.sync.aligned.m16n8k16.row.col.f32.bf16.bf16.f32 "
        "{%0,%1,%2,%3}, {%4,%5,%6,%7}, {%8,%9}, {%0,%1,%2,%3};"
        : "+f"(d[0]), "+f"(d[1]), "+f"(d[2]), "+f"(d[3])
        : "r"(a[0]), "r"(a[1]), "r"(a[2]), "r"(a[3]), "r"(b[0]), "r"(b[1]));
}

// C[M,2048] = A[M,512] @ W[2048,512]^T + bias via 3xTF32 tensor-core MMA.
__global__ __launch_bounds__(256) void gemm_tf32_kernel(
    const float* __restrict__ A, const float* __restrict__ W,
    const float* __restrict__ bias, float* __restrict__ C)
{
    extern __shared__ float gsm[];
    float* Ahs = gsm;
    float* Als = Ahs + GK * GSTRIDE;
    float* Whs = Als + GK * GSTRIDE;
    float* Wls = Whs + GK * GSTRIDE;

    const int tid  = threadIdx.x;
    const int lane = tid & 31;
    const int w    = tid >> 5;
    const int wm   = w >> 2;
    const int wn   = w & 3;
    const int lg   = lane >> 2;
    const int lt   = lane & 3;
    const int m0   = blockIdx.y * 128;
    const int n0   = blockIdx.x * 128;

    const int mr = tid >> 1;
    const int kq = (tid & 1) << 4;
    const float* Arow = A + (size_t)(m0 + mr) * DD;
    const float* Wrow = W + (size_t)(n0 + mr) * DD;

    float acc[4][4][4];
    #pragma unroll
    for (int mt = 0; mt < 4; mt++)
        #pragma unroll
        for (int nt = 0; nt < 4; nt++)
            #pragma unroll
            for (int i = 0; i < 4; i++) acc[mt][nt][i] = 0.f;

    for (int kc = 0; kc < DD; kc += GK) {
        __syncthreads();
        #pragma unroll
        for (int i = 0; i < 4; i++) {
            const int kk = kq + 4 * i;
            float4 va = *reinterpret_cast<const float4*>(Arow + kc + kk);
            float4 vw = *reinterpret_cast<const float4*>(Wrow + kc + kk);
            float h;
            h = tf32_hi(va.x); Ahs[(kk+0)*GSTRIDE + mr] = h; Als[(kk+0)*GSTRIDE + mr] = va.x - h;
            h = tf32_hi(va.y); Ahs[(kk+1)*GSTRIDE + mr] = h; Als[(kk+1)*GSTRIDE + mr] = va.y - h;
            h = tf32_hi(va.z); Ahs[(kk+2)*GSTRIDE + mr] = h; Als[(kk+2)*GSTRIDE + mr] = va.z - h;
            h = tf32_hi(va.w); Ahs[(kk+3)*GSTRIDE + mr] = h; Als[(kk+3)*GSTRIDE + mr] = va.w - h;
            h = tf32_hi(vw.x); Whs[(kk+0)*GSTRIDE + mr] = h; Wls[(kk+0)*GSTRIDE + mr] = vw.x - h;
            h = tf32_hi(vw.y); Whs[(kk+1)*GSTRIDE + mr] = h; Wls[(kk+1)*GSTRIDE + mr] = vw.y - h;
            h = tf32_hi(vw.z); Whs[(kk+2)*GSTRIDE + mr] = h; Wls[(kk+2)*GSTRIDE + mr] = vw.z - h;
            h = tf32_hi(vw.w); Whs[(kk+3)*GSTRIDE + mr] = h; Wls[(kk+3)*GSTRIDE + mr] = vw.w - h;
        }
        __syncthreads();

        #pragma unroll
        for (int k8 = 0; k8 < GK; k8 += 8) {
            unsigned ah[4][4], al[4][4], bh[4][2], bl[4][2];
            const int ka = (k8 + lt) * GSTRIDE;
            const int kb = (k8 + lt + 4) * GSTRIDE;
            #pragma unroll
            for (int mt = 0; mt < 4; mt++) {
                const int mb = wm * 64 + mt * 16 + lg;
                ah[mt][0] = __float_as_uint(Ahs[ka + mb]);
                ah[mt][1] = __float_as_uint(Ahs[ka + mb + 8]);
                ah[mt][2] = __float_as_uint(Ahs[kb + mb]);
                ah[mt][3] = __float_as_uint(Ahs[kb + mb + 8]);
                al[mt][0] = __float_as_uint(Als[ka + mb]);
                al[mt][1] = __float_as_uint(Als[ka + mb + 8]);
                al[mt][2] = __float_as_uint(Als[kb + mb]);
                al[mt][3] = __float_as_uint(Als[kb + mb + 8]);
            }
            #pragma unroll
            for (int nt = 0; nt < 4; nt++) {
                const int nb = wn * 32 + nt * 8 + lg;
                bh[nt][0] = __float_as_uint(Whs[ka + nb]);
                bh[nt][1] = __float_as_uint(Whs[kb + nb]);
                bl[nt][0] = __float_as_uint(Wls[ka + nb]);
                bl[nt][1] = __float_as_uint(Wls[kb + nb]);
            }
            #pragma unroll
            for (int mt = 0; mt < 4; mt++)
                #pragma unroll
                for (int nt = 0; nt < 4; nt++)
                    mma_tf32(acc[mt][nt], ah[mt], bh[nt]);
            #pragma unroll
            for (int mt = 0; mt < 4; mt++)
                #pragma unroll
                for (int nt = 0; nt < 4; nt++)
                    mma_tf32(acc[mt][nt], al[mt], bh[nt]);
            #pragma unroll
            for (int mt = 0; mt < 4; mt++)
                #pragma unroll
                for (int nt = 0; nt < 4; nt++)
                    mma_tf32(acc[mt][nt], ah[mt], bl[nt]);
        }
    }

    #pragma unroll
    for (int mt = 0; mt < 4; mt++) {
        const int row = m0 + wm * 64 + mt * 16 + lg;
        #pragma unroll
        for (int nt = 0; nt < 4; nt++) {
            const int col = n0 + wn * 32 + nt * 8 + lt * 2;
            float2 bs = *reinterpret_cast<const float2*>(bias + col);
            float2 o0 = make_float2(acc[mt][nt][0] + bs.x, acc[mt][nt][1] + bs.y);
            float2 o1 = make_float2(acc[mt][nt][2] + bs.x, acc[mt][nt][3] + bs.y);
            *reinterpret_cast<float2*>(C + (size_t)row * G4 + col)       = o0;
            *reinterpret_cast<float2*>(C + (size_t)(row + 8) * G4 + col) = o1;
        }
    }
}

// Fused two-layer pipelined recurrence, bf16-split tensor-core compute.
// 12 warps: 0-3 L0 (t=s), 4-7 L1 y0-part, 8-11 L1 h1-part (t=s-1).
// Per warp: 8 k-tiles(16) x 2 m-tiles(batch) x 2 n-tiles(gate rows) x 3 terms.
// C frags land in the same red0/red1 layout as the scalar version; tails,
// i2h prefetch, and the all-to-all flag barrier are unchanged from R8.
__global__ __launch_bounds__(NTHR, 1) void lstm_fused_kernel(
    const float* __restrict__ Wh0, const float* __restrict__ bh0,
    const float* __restrict__ Wi1, const float* __restrict__ bi1,
    const float* __restrict__ Wh1, const float* __restrict__ bh1,
    const float* __restrict__ i2h, float* __restrict__ yout,
    float* __restrict__ hc_out)
{
    extern __shared__ float sm[];
    unsigned* wf0h = reinterpret_cast<unsigned*>(sm);       // 4096 u32
    unsigned* wf0l = wf0h + 4096;                           // 4096
    unsigned* wf1h = wf0l + 4096;                           // 8192
    unsigned* wf1l = wf1h + 8192;                           // 8192
    float* red0 = sm + 24576;                               // 16*32*4
    float* red1 = red0 + 2048;                              // 16*32*8
    float* pres = red1 + 4096;                              // 512
    float* bs0  = pres + 512;                               // 16
    float* bs1  = bs0 + 16;                                 // 16
    float* cs0  = bs1 + 16;                                 // 128
    float* cs1  = cs0 + 128;                                // 128

    const int tid = threadIdx.x;
    const int bid = blockIdx.x;
    const int j0 = bid * JC;
    const int lane = tid & 31;
    const int gid = lane >> 2;       // 0..7
    const int tig = lane & 3;        // 0..3

    // ---- stage weights: bf16 hi/lo in B-fragment order ----
    // wf[(kt*2+nt)*64 + lane*2 + {0,1}]: b0 = (k=kt*16+tig*2{,+1}, rl=nt*8+gid),
    //                                    b1 = k+8{,+9}
    for (int t = tid; t < 32 * 2 * 32; t += NTHR) {          // L0: 32 ktiles
        int kt = t >> 6, nt = (t >> 5) & 1, ln = t & 31;
        int rl = nt * 8 + (ln >> 2);
        int g = rl >> 2, jj = rl & 3;
        const float* wr = Wh0 + (size_t)(g * HH + j0 + jj) * HH;
        int kk = kt * 16 + (ln & 3) * 2;
        unsigned short h0_, l0_, h1_, l1_, h8_, l8_, h9_, l9_;
        bf_split(wr[kk],     h0_, l0_);
        bf_split(wr[kk + 1], h1_, l1_);
        bf_split(wr[kk + 8], h8_, l8_);
        bf_split(wr[kk + 9], h9_, l9_);
        int o = (kt * 2 + nt) * 64 + ln * 2;
        wf0h[o]     = bf_pack(h0_, h1_);
        wf0h[o + 1] = bf_pack(h8_, h9_);
        wf0l[o]     = bf_pack(l0_, l1_);
        wf0l[o + 1] = bf_pack(l8_, l9_);
    }
    for (int t = tid; t < 64 * 2 * 32; t += NTHR) {          // L1: 64 ktiles
        int kt = t >> 6, nt = (t >> 5) & 1, ln = t & 31;
        int rl = nt * 8 + (ln >> 2);
        int g = rl >> 2, jj = rl & 3;
        int kk = kt * 16 + (ln & 3) * 2;
        const float* wr = (kk < 512)
            ? Wi1 + (size_t)(g * HH + j0 + jj) * HH
            : Wh1 + (size_t)(g * HH + j0 + jj) * HH - 512;
        unsigned short h0_, l0_, h1_, l1_, h8_, l8_, h9_, l9_;
        bf_split(wr[kk],     h0_, l0_);
        bf_split(wr[kk + 1], h1_, l1_);
        bf_split(wr[kk + 8], h8_, l8_);
        bf_split(wr[kk + 9], h9_, l9_);
        int o = (kt * 2 + nt) * 64 + ln * 2;
        wf1h[o]     = bf_pack(h0_, h1_);
        wf1h[o + 1] = bf_pack(h8_, h9_);
        wf1l[o]     = bf_pack(l0_, l1_);
        wf1l[o + 1] = bf_pack(l8_, l9_);
    }
    if (tid < 16) {
        int gg = tid >> 2, jx = tid & 3;
        bs0[tid] = bh0[gg * HH + j0 + jx];
        bs1[tid] = bi1[gg * HH + j0 + jx] + bh1[gg * HH + j0 + jx];
    }
    if (tid < 128) { cs0[tid] = 0.f; cs1[tid] = 0.f; }
    __syncthreads();

    const int w = tid >> 5;          // warp 0..11
    float4* pres4 = reinterpret_cast<float4*>(pres);

    for (int s = 0; s <= TT; s++) {
        // coalesced i2h prefetch (L0 tail input)
        float4 preq = make_float4(0.f, 0.f, 0.f, 0.f);
        if (tid < 128 && s < TT) {
            const int b_ = tid & 31, g_ = tid >> 5;
            preq = __ldcg(reinterpret_cast<const float4*>(
                i2h + ((size_t)b_ * TT + s) * G4 + (g_ << 9) + j0));
        }

        // ---- tensor FMA phase ----
        {
            const unsigned short *hh = nullptr, *hl = nullptr;
            const unsigned *bfh = nullptr, *bfl = nullptr;
            int kth = 0, ktw = 0;
            bool active = false;
            if (w < 4) {                    // L0: h0(s-1)
                if (s < TT) {
                    active = true;
                    hh = g_h0h[s & 1]; hl = g_h0l[s & 1];
                    bfh = wf0h; bfl = wf0l;
                    kth = w * 8; ktw = w * 8;
                }
            } else if (s >= 1) {
                active = true;
                bfh = wf1h; bfl = wf1l;
                if (w < 8) {                // L1 y0-part: h0(s-1) buffer parity s&1
                    hh = g_h0h[s & 1]; hl = g_h0l[s & 1];
                    kth = (w - 4) * 8; ktw = (w - 4) * 8;
                } else {                    // L1 h1-part: h1(s-2)
                    hh = g_h1h[(s - 1) & 1]; hl = g_h1l[(s - 1) & 1];
                    kth = (w - 8) * 8; ktw = 32 + (w - 8) * 8;
                }
            }
            if (active) {
                float c[2][2][4];
                #pragma unroll
                for (int mt = 0; mt < 2; mt++)
                    #pragma unroll
                    for (int nt = 0; nt < 2; nt++)
                        #pragma unroll
                        for (int i = 0; i < 4; i++) c[mt][nt][i] = 0.f;

                #pragma unroll
                for (int k = 0; k < 8; k++) {
                    unsigned bh[2][2], bl[2][2];
                    #pragma unroll
                    for (int nt = 0; nt < 2; nt++) {
                        uint2 vh = *reinterpret_cast<const uint2*>(
                            bfh + ((ktw + k) * 2 + nt) * 64 + lane * 2);
                        uint2 vl = *reinterpret_cast<const uint2*>(
                            bfl + ((ktw + k) * 2 + nt) * 64 + lane * 2);
                        bh[nt][0] = vh.x; bh[nt][1] = vh.y;
                        bl[nt][0] = vl.x; bl[nt][1] = vl.y;
                    }
                    const int kk = (kth + k) * 16 + tig * 2;
                    #pragma unroll
                    for (int mt = 0; mt < 2; mt++) {
                        const int b0r = mt * 16 + gid;
                        const int o = b0r * HH + kk;
                        unsigned ah[4], al[4];
                        ah[0] = __ldcg(reinterpret_cast<const unsigned*>(hh + o));
                        ah[1] = __ldcg(reinterpret_cast<const unsigned*>(hh + o + 8 * HH));
                        ah[2] = __ldcg(reinterpret_cast<const unsigned*>(hh + o + 8));
                        ah[3] = __ldcg(reinterpret_cast<const unsigned*>(hh + o + 8 * HH + 8));
                        al[0] = __ldcg(reinterpret_cast<const unsigned*>(hl + o));
                        al[1] = __ldcg(reinterpret_cast<const unsigned*>(hl + o + 8 * HH));
                        al[2] = __ldcg(reinterpret_cast<const unsigned*>(hl + o + 8));
                        al[3] = __ldcg(reinterpret_cast<const unsigned*>(hl + o + 8 * HH + 8));
                        #pragma unroll
                        for (int nt = 0; nt < 2; nt++) {
                            mma_bf16(c[mt][nt], ah, bh[nt]);
                            mma_bf16(c[mt][nt], al, bh[nt]);
                            mma_bf16(c[mt][nt], ah, bl[nt]);
                        }
                    }
                }
                // scatter C frags into red (same layout as scalar version)
                // c0:(b, rl) c1:(b, rl+1) c2:(b+8, rl) c3:(b+8, rl+1)
                #pragma unroll
                for (int mt = 0; mt < 2; mt++) {
                    const int b = mt * 16 + gid;
                    #pragma unroll
                    for (int nt = 0; nt < 2; nt++) {
                        const int rl = nt * 8 + tig * 2;
                        if (w < 4) {
                            red0[(rl * 32 + b) * 4 + w]           = c[mt][nt][0];
                            red0[((rl + 1) * 32 + b) * 4 + w]     = c[mt][nt][1];
                            red0[(rl * 32 + b + 8) * 4 + w]       = c[mt][nt][2];
                            red0[((rl + 1) * 32 + b + 8) * 4 + w] = c[mt][nt][3];
                        } else {
                            const int wc = w - 4;
                            red1[(rl * 32 + b) * 8 + wc]           = c[mt][nt][0];
                            red1[((rl + 1) * 32 + b) * 8 + wc]     = c[mt][nt][1];
                            red1[(rl * 32 + b + 8) * 8 + wc]       = c[mt][nt][2];
                            red1[((rl + 1) * 32 + b + 8) * 8 + wc] = c[mt][nt][3];
                        }
                    }
                }
            }
        }
        if (tid < 128 && s < TT) pres4[tid] = preq;
        __syncthreads();

        // ---- tails: tid<128 -> L0, tid in [128,256) -> L1 ----
        float   y_val = 0.f;
        size_t  y_idx = 0;
        bool    y_pend = false;

        if (tid < 128) {
            if (s < TT) {
                const int b = tid & 31, jj = tid >> 5;
                const int j = j0 + jj;
                float gate[4];
                #pragma unroll
                for (int g = 0; g < 4; g++) {
                    const int rr = g * 4 + jj;
                    float4 q0 = *reinterpret_cast<const float4*>(&red0[(rr * 32 + b) * 4]);
                    float pre = pres[(g * 32 + b) * 4 + jj];
                    gate[g] = ((q0.x + q0.y) + (q0.z + q0.w)) + pre + bs0[rr];
                }
                float ig = sigf(gate[0]);
                float fg = sigf(gate[1]);
                float cg = tanhf_(gate[2]);
                float og = sigf(gate[3]);
                float c_new = fmaf(fg, cs0[tid], ig * cg);
                float h_new = og * tanhf_(c_new);
                cs0[tid] = c_new;
                unsigned short hh_, hl_;
                bf_split(h_new, hh_, hl_);
                const int p = (s + 1) & 1;
                g_h0h[p][b * HH + j] = hh_;
                g_h0l[p][b * HH + j] = hl_;
                if (s == TT - 1) {
                    hc_out[(size_t)0 * BB * HH + b * HH + j] = h_new;
                    hc_out[(size_t)2 * BB * HH + b * HH + j] = c_new;
                }
            }
        } else if (tid < 256) {
            if (s >= 1) {
                const int tt_ = tid - 128;
                const int b = tt_ & 31, jj = tt_ >> 5;
                const int j = j0 + jj;
                const int t = s - 1;
                float gate[4];
                #pragma unroll
                for (int g = 0; g < 4; g++) {
                    const int rr = g * 4 + jj;
                    const float4* rp = reinterpret_cast<const float4*>(&red1[(rr * 32 + b) * 8]);
                    float4 q0 = rp[0], q1 = rp[1];
                    gate[g] = ((q0.x + q0.y) + (q0.z + q0.w))
                            + ((q1.x + q1.y) + (q1.z + q1.w)) + bs1[rr];
                }
                float ig = sigf(gate[0]);
                float fg = sigf(gate[1]);
                float cg = tanhf_(gate[2]);
                float og = sigf(gate[3]);
                float c_new = fmaf(fg, cs1[tt_], ig * cg);
                float h_new = og * tanhf_(c_new);
                cs1[tt_] = c_new;
                unsigned short hh_, hl_;
                bf_split(h_new, hh_, hl_);
                g_h1h[s & 1][b * HH + j] = hh_;
                g_h1l[s & 1][b * HH + j] = hl_;
                y_val = h_new;
                y_idx = ((size_t)b * TT + t) * HH + j;
                if (s < TT) {
                    y_pend = true;
                } else {
                    yout[y_idx] = h_new;
                }
                if (t == TT - 1) {
                    hc_out[(size_t)1 * BB * HH + b * HH + j] = h_new;
                    hc_out[(size_t)3 * BB * HH + b * HH + j] = c_new;
                }
            }
        }

        // ---- all-to-all flag barrier ----
        if (s < TT) {
            const unsigned e = (unsigned)(s + 1);
            __syncthreads();
            if (tid == 0)
                asm volatile("st.release.gpu.u32 [%0], %1;"
                             :: "l"(&g_flags[bid * 32]), "r"(e) : "memory");
            if (y_pend) yout[y_idx] = y_val;
            if (tid < NCTA) {
                unsigned v;
                do {
                    asm volatile("ld.acquire.gpu.u32 %0, [%1];"
                                 : "=r"(v) : "l"(&g_flags[tid * 32]) : "memory");
                } while (v < e);
            }
            __syncthreads();
        }
    }
}

extern "C" void kernel_launch(void* const* d_in, const int* in_sizes, int n_in,
                              void* d_out, int out_size)
{
    (void)in_sizes; (void)n_in; (void)out_size;
    const float* x   = (const float*)d_in[0];
    const float* Wi0 = (const float*)d_in[1];
    const float* bi0 = (const float*)d_in[2];
    const float* Wh0 = (const float*)d_in[3];
    const float* bh0 = (const float*)d_in[4];
    const float* Wi1 = (const float*)d_in[5];
    const float* bi1 = (const float*)d_in[6];
    const float* Wh1 = (const float*)d_in[7];
    const float* bh1 = (const float*)d_in[8];
    float* out = (float*)d_out;

    float* i2h_p;
    cudaGetSymbolAddress((void**)&i2h_p, g_i2h);

    const int SMEM_G = 4 * GK * GSTRIDE * (int)sizeof(float);
    cudaFuncSetAttribute(gemm_tf32_kernel,
                         cudaFuncAttributeMaxDynamicSharedMemorySize, SMEM_G);

    const int SMEM = (24576 + 2048 + 4096 + 512 + 16 + 16 + 128 + 128)
                     * (int)sizeof(float);
    cudaFuncSetAttribute(lstm_fused_kernel,
                         cudaFuncAttributeMaxDynamicSharedMemorySize, SMEM);

    dim3 ggrid(G4 / 128, (BB * TT) / 128);
    float* hc = out + (size_t)BB * TT * HH;

    gemm_tf32_kernel<<<ggrid, 256, SMEM_G>>>(x, Wi0, bi0, i2h_p);
    init_state_kernel<<<64, 256>>>();
    lstm_fused_kernel<<<NCTA, NTHR, SMEM>>>(Wh0, bh0, Wi1, bi1, Wh1, bh1,
                                            i2h_p, out, hc);
}